// round 12
// baseline (speedup 1.0000x reference)
#include <cuda_runtime.h>

#define NEG 0.2f
typedef unsigned long long ull;

// Inter-stage scratch (allocation-free rule: __device__ globals)
__device__ float g_buf1[1024 * 4 * 4096];   // [B][4][16^3]
__device__ float g_buf2[1024 * 8 * 512];    // [B][8][8^3]

__device__ __forceinline__ float lrelu(float x) { return x >= 0.0f ? x : NEG * x; }

__device__ __forceinline__ ull dup2(float v) {
    ull d; asm("mov.b64 %0, {%1, %1};" : "=l"(d) : "f"(v)); return d;
}
__device__ __forceinline__ void ffma2(ull& a, ull x, ull y) {
    asm("fma.rn.f32x2 %0, %1, %2, %0;" : "+l"(a) : "l"(x), "l"(y));
}
__device__ __forceinline__ void unpk(ull d, float& lo, float& hi) {
    asm("mov.b64 {%0, %1}, %2;" : "=f"(lo), "=f"(hi) : "l"(d));
}

// Load one 4-wide halo row from an NxN plane and dup each value into f32x2.
template <int N>
__device__ __forceinline__ void row_dup(const float* __restrict__ plane,
                                        int y, int e, bool mok, bool rok, ull* rd)
{
    const bool ok = (unsigned)y < (unsigned)N;
    const float2 zz = make_float2(0.0f, 0.0f);
    const float* row = plane + y * N;
    const float2 m = (ok && mok) ? *(const float2*)(row + e - 2) : zz;
    const float2 c = ok           ? *(const float2*)(row + e)     : zz;
    const float2 r = (ok && rok) ? *(const float2*)(row + e + 2) : zz;
    rd[0] = dup2(m.y); rd[1] = dup2(c.x); rd[2] = dup2(c.y); rd[3] = dup2(r.x);
}

// One z-slice (role DZ in the 4-slice pooled patch) of a 3^3 conv for NP
// oc-pairs. Values dup'd ONCE per slice; two dup'd rows march with kh.
// Weights: ull pairs {w_oc0, w_oc1}, wb[g*wstride + t].
// acc[g][jz*4 + jy*2 + jx] = pool position, oc pair packed in lanes.
template <int N, int NP, int DZ>
__device__ __forceinline__ void conv_slice_dup(const float* __restrict__ plane,
                                               int px, int py,
                                               const ull* __restrict__ wb, int wstride,
                                               ull (&acc)[NP][8])
{
    const int by = 2 * py - 1, e = 2 * px;
    const bool mok = px >= 1, rok = (2 * px + 2) < N;
    ull r0[4], r1[4];
    row_dup<N>(plane, by, e, mok, rok, r0);
    #pragma unroll
    for (int kh = 0; kh < 3; kh++) {
        ull* rlo = (kh & 1) ? r1 : r0;       // row kh
        ull* rhi = (kh & 1) ? r0 : r1;       // row kh+1
        row_dup<N>(plane, by + kh + 1, e, mok, rok, rhi);
        #pragma unroll
        for (int kd = 0; kd < 3; kd++) {
            const int jz = DZ - kd;          // compile-time pruned
            if (jz < 0 || jz > 1) continue;
            #pragma unroll
            for (int kw = 0; kw < 3; kw++) {
                const int t = (kd * 3 + kh) * 3 + kw;
                ull wv[NP];
                #pragma unroll
                for (int g = 0; g < NP; g++) wv[g] = wb[g * wstride + t];
                #pragma unroll
                for (int jy = 0; jy < 2; jy++) {
                    const ull* rd = jy ? rhi : rlo;
                    #pragma unroll
                    for (int jx = 0; jx < 2; jx++)
                        #pragma unroll
                        for (int g = 0; g < NP; g++)
                            ffma2(acc[g][jz * 4 + jy * 2 + jx], wv[g], rd[kw + jx]);
                }
            }
        }
    }
}

// Full 4-slice pooled-cell conv (planes contiguous, stride PS floats, all in-bounds).
template <int N, int NP>
__device__ __forceinline__ void conv_cell4(const float* __restrict__ p0, int PS,
                                           int px, int py,
                                           const ull* __restrict__ wb, int wstride,
                                           ull (&acc)[NP][8])
{
    conv_slice_dup<N, NP, 0>(p0,          px, py, wb, wstride, acc);
    conv_slice_dup<N, NP, 1>(p0 + PS,     px, py, wb, wstride, acc);
    conv_slice_dup<N, NP, 2>(p0 + 2 * PS, px, py, wb, wstride, acc);
    conv_slice_dup<N, NP, 3>(p0 + 3 * PS, px, py, wb, wstride, acc);
}

__device__ __forceinline__ void finish_pair(const ull a[8], float blo, float bhi,
                                            float& olo, float& ohi) {
    float l, h, ml, mh;
    unpk(a[0], ml, mh);
    #pragma unroll
    for (int j = 1; j < 8; j++) {
        unpk(a[j], l, h);
        ml = fmaxf(ml, l); mh = fmaxf(mh, h);
    }
    olo = lrelu(ml + blo); ohi = lrelu(mh + bhi);
}

// ============ K1: conv1 (1->4) @32^3, 4-way z-split, 4 CTAs/SM ============
__global__ __launch_bounds__(256, 4)
void k1_conv1(const float* __restrict__ vox, const float* __restrict__ w1,
              const float* __restrict__ b1)
{
    extern __shared__ float sm[];
    float* slab = sm;                           // 10 planes * 1024
    ull*   w1u  = (ull*)(sm + 10240);           // 54 pairs {w_2g, w_2g+1}[27]
    const int tid = threadIdx.x;
    const int b = blockIdx.x >> 2, q = blockIdx.x & 3;
    {
        const float4* v4 = (const float4*)(vox + (size_t)b * 32768);
        float4* s4 = (float4*)slab;
        for (int i = tid; i < 2560; i += 256) {
            const int s = i >> 8, z = 8 * q - 1 + s;
            s4[i] = ((unsigned)z < 32u) ? v4[(z << 8) + (i & 255)]
                                        : make_float4(0, 0, 0, 0);
        }
        float2* wd = (float2*)w1u;
        for (int i = tid; i < 54; i += 256) {
            const int g = i / 27, t = i % 27;
            wd[i] = make_float2(w1[(2 * g) * 27 + t], w1[(2 * g + 1) * 27 + t]);
        }
    }
    __syncthreads();
    float bia[4];
    #pragma unroll
    for (int g = 0; g < 4; g++) bia[g] = __ldg(&b1[g]);

    #pragma unroll 1
    for (int it = 0; it < 4; it++) {
        const int c = tid + (it << 8);
        const int px = c & 15, py = (c >> 4) & 15, pzl = c >> 8;   // pzl 0..3
        ull acc[2][8];
        #pragma unroll
        for (int g = 0; g < 2; g++)
            #pragma unroll
            for (int j = 0; j < 8; j++) acc[g][j] = 0ull;
        conv_cell4<32, 2>(slab + ((2 * pzl) << 10), 1024, px, py, w1u, 27, acc);
        #pragma unroll
        for (int g = 0; g < 2; g++) {
            float olo, ohi;
            finish_pair(acc[g], bia[2 * g], bia[2 * g + 1], olo, ohi);
            const int cell = ((q * 4 + pzl) << 8) + (py << 4) + px;
            g_buf1[(((size_t)b * 4 + 2 * g) << 12) + cell]     = olo;
            g_buf1[(((size_t)b * 4 + 2 * g + 1) << 12) + cell] = ohi;
        }
    }
}

// ============ K2: conv2 (4->8) @16^3, z-split, 4 CTAs/SM ============
__global__ __launch_bounds__(256, 4)
void k2_conv2(const float* __restrict__ w2, const float* __restrict__ b2)
{
    extern __shared__ float sm[];
    float* slab = sm;                           // 4 ic * 10 planes * 256
    ull*   w2u  = (ull*)(sm + 10240);           // 432 pairs [g(4)][ic(4)][27]
    const int tid = threadIdx.x;
    const int b = blockIdx.x >> 1, h = blockIdx.x & 1;
    {
        const float4* g4 = (const float4*)g_buf1;
        float4* s4 = (float4*)slab;
        for (int i = tid; i < 2560; i += 256) {
            const int ic = i / 640, rem = i - ic * 640;
            const int s = rem >> 6, z = 8 * h - 1 + s;
            s4[i] = ((unsigned)z < 16u)
                ? g4[(((size_t)b * 4 + ic) << 10) + (z << 6) + (rem & 63)]
                : make_float4(0, 0, 0, 0);
        }
        float2* wd = (float2*)w2u;
        for (int i = tid; i < 432; i += 256) {
            const int g = i / 108, rem = i % 108, ic = rem / 27, t = rem % 27;
            wd[i] = make_float2(w2[((2 * g) * 4 + ic) * 27 + t],
                                w2[((2 * g + 1) * 4 + ic) * 27 + t]);
        }
    }
    __syncthreads();
    const int px = tid & 7, py = (tid >> 3) & 7, pzl = tid >> 6;

    #pragma unroll 1
    for (int opass = 0; opass < 2; opass++) {
        ull acc[2][8];
        #pragma unroll
        for (int g = 0; g < 2; g++)
            #pragma unroll
            for (int j = 0; j < 8; j++) acc[g][j] = 0ull;
        #pragma unroll 1
        for (int ic = 0; ic < 4; ic++) {
            conv_cell4<16, 2>(slab + ic * 2560 + ((2 * pzl) << 8), 256, px, py,
                              w2u + ((opass * 2) * 4 + ic) * 27, 108, acc);
        }
        #pragma unroll
        for (int g = 0; g < 2; g++) {
            const int oc0 = 2 * (opass * 2 + g);
            float olo, ohi;
            finish_pair(acc[g], __ldg(&b2[oc0]), __ldg(&b2[oc0 + 1]), olo, ohi);
            const int cell = ((4 * h + pzl) << 6) + (py << 3) + px;
            g_buf2[(((size_t)b * 8 + oc0) << 9) + cell]     = olo;
            g_buf2[(((size_t)b * 8 + oc0 + 1) << 9) + cell] = ohi;
        }
    }
}

// ============ K3: conv3..conv5 + heads, w4 staged in halves, 4 CTAs/SM ======
#define ZPAD  0            // 64 zeros (OOB z-plane source)
#define R0    64           // phase A: {w3 pairs 3456 | buf2 4096}; phase B: w4-half 6912
#define BUF3q 7616         // 1024 (16ch * 4^3)
#define BUF4q 8640         // 256  (32ch * 2^3)
#define FEATq 8896         // 64
#define HSq   8960         // 320
#define K3TOT 9280         // floats -> 37120 B

__global__ __launch_bounds__(256, 4)
void k3_tail(const float* __restrict__ w3, const float* __restrict__ b3,
             const float* __restrict__ w4, const float* __restrict__ b4,
             const float* __restrict__ w5, const float* __restrict__ b5,
             const float* __restrict__ hW1, const float* __restrict__ hb1,
             const float* __restrict__ hW2, const float* __restrict__ hb2,
             const float* __restrict__ hW3, const float* __restrict__ hb3,
             float* __restrict__ out)
{
    extern __shared__ float sm[];
    const int tid = threadIdx.x, b = blockIdx.x;
    ull*   w3u  = (ull*)(sm + R0);              // 1728 pairs [g(8)][ic(8)][27]
    float* buf2 = sm + R0 + 3456;
    {
        if (tid < 64) sm[ZPAD + tid] = 0.0f;
        const float4* g4 = (const float4*)(g_buf2 + (size_t)b * 4096);
        float4* s4 = (float4*)buf2;
        for (int i = tid; i < 1024; i += 256) s4[i] = g4[i];
        float2* wd = (float2*)w3u;
        for (int i = tid; i < 1728; i += 256) {
            const int g = i / 216, rem = i % 216, ic = rem / 27, t = rem % 27;
            wd[i] = make_float2(w3[((2 * g) * 8 + ic) * 27 + t],
                                w3[((2 * g + 1) * 8 + ic) * 27 + t]);
        }
    }
    __syncthreads();

    // conv3 (8->16) @8^3 -> buf3 [16][4^3]
    {
        const int grp = tid >> 6, cell = tid & 63;
        const int px = cell & 3, py = (cell >> 2) & 3, pz = cell >> 4;
        ull acc[2][8];
        #pragma unroll
        for (int g = 0; g < 2; g++)
            #pragma unroll
            for (int j = 0; j < 8; j++) acc[g][j] = 0ull;
        const int z0 = 2 * pz - 1;
        #pragma unroll 1
        for (int ic = 0; ic < 8; ic++) {
            const float* chan = buf2 + ic * 512;
            const ull*   wp   = w3u + ((2 * grp) * 8 + ic) * 27;
            conv_slice_dup<8, 2, 0>(((unsigned)z0       < 8u) ? chan + (z0 << 6)       : sm + ZPAD, px, py, wp, 216, acc);
            conv_slice_dup<8, 2, 1>(chan + ((z0 + 1) << 6), px, py, wp, 216, acc);
            conv_slice_dup<8, 2, 2>(chan + ((z0 + 2) << 6), px, py, wp, 216, acc);
            conv_slice_dup<8, 2, 3>(((unsigned)(z0 + 3) < 8u) ? chan + ((z0 + 3) << 6) : sm + ZPAD, px, py, wp, 216, acc);
        }
        #pragma unroll
        for (int g = 0; g < 2; g++) {
            const int oc0 = 4 * grp + 2 * g;
            float olo, ohi;
            finish_pair(acc[g], __ldg(&b3[oc0]), __ldg(&b3[oc0 + 1]), olo, ohi);
            sm[BUF3q + oc0 * 64 + cell]       = olo;
            sm[BUF3q + (oc0 + 1) * 64 + cell] = ohi;
        }
    }

    // conv4 (16->32) @4^3 -> buf4 [32][2^3], w4 staged in two 16-oc halves.
    // 8 pairs x 8 cells x 4 ic-groups = 256 threads; quad-shfl reduce.
    #pragma unroll 1
    for (int half = 0; half < 2; half++) {
        __syncthreads();                        // prior readers of R0 / BUF3q done
        {
            float2* wd = (float2*)(sm + R0);    // [p(8)][ic(16)][27]
            for (int i = tid; i < 3456; i += 256) {
                const int p = i / 432, rem = i % 432, ic = rem / 27, t = rem % 27;
                const int oc0 = half * 16 + 2 * p;
                wd[i] = make_float2(w4[(oc0 * 16 + ic) * 27 + t],
                                    w4[((oc0 + 1) * 16 + ic) * 27 + t]);
            }
        }
        __syncthreads();
        const ull* w4u = (const ull*)(sm + R0);
        const int p = tid >> 5, cell = (tid >> 2) & 7, icg = tid & 3;
        const int px = cell & 1, py = (cell >> 1) & 1, pz = cell >> 2;
        ull acc[1][8];
        #pragma unroll
        for (int j = 0; j < 8; j++) acc[0][j] = 0ull;
        const int z0 = 2 * pz - 1;
        #pragma unroll 1
        for (int k = 0; k < 4; k++) {
            const int ic = icg * 4 + k;
            const float* chan = sm + BUF3q + ic * 64;
            const ull*   wp   = w4u + (p * 16 + ic) * 27;
            conv_slice_dup<4, 1, 0>(((unsigned)z0       < 4u) ? chan + (z0 << 4)       : sm + ZPAD, px, py, wp, 0, acc);
            conv_slice_dup<4, 1, 1>(chan + ((z0 + 1) << 4), px, py, wp, 0, acc);
            conv_slice_dup<4, 1, 2>(chan + ((z0 + 2) << 4), px, py, wp, 0, acc);
            conv_slice_dup<4, 1, 3>(((unsigned)(z0 + 3) < 4u) ? chan + ((z0 + 3) << 4) : sm + ZPAD, px, py, wp, 0, acc);
        }
        float mlo = -1e30f, mhi = -1e30f;
        #pragma unroll
        for (int j = 0; j < 8; j++) {
            float lo, hi; unpk(acc[0][j], lo, hi);
            lo += __shfl_xor_sync(0xffffffffu, lo, 1);
            lo += __shfl_xor_sync(0xffffffffu, lo, 2);
            hi += __shfl_xor_sync(0xffffffffu, hi, 1);
            hi += __shfl_xor_sync(0xffffffffu, hi, 2);
            mlo = fmaxf(mlo, lo); mhi = fmaxf(mhi, hi);
        }
        if (icg == 0) {
            const int oc0 = half * 16 + 2 * p;
            sm[BUF4q + oc0 * 8 + cell]       = lrelu(mlo + __ldg(&b4[oc0]));
            sm[BUF4q + (oc0 + 1) * 8 + cell] = lrelu(mhi + __ldg(&b4[oc0 + 1]));
        }
    }
    __syncthreads();

    // conv5 (32->64) @2^3 -> feat[64]
    {
        const int ocl = tid >> 2, icg = tid & 3;
        float a[8];
        #pragma unroll
        for (int j = 0; j < 8; j++) a[j] = 0.0f;
        #pragma unroll 1
        for (int k = 0; k < 8; k++) {
            const int ic = icg * 8 + k;
            float xin[8];
            #pragma unroll
            for (int j = 0; j < 8; j++) xin[j] = sm[BUF4q + ic * 8 + j];
            float wr[27];
            const float* wp = w5 + (ocl * 32 + ic) * 27;
            #pragma unroll
            for (int t = 0; t < 27; t++) wr[t] = __ldg(&wp[t]);
            #pragma unroll
            for (int p8 = 0; p8 < 8; p8++) {
                const int oz = p8 >> 2, oy = (p8 >> 1) & 1, ox = p8 & 1;
                #pragma unroll
                for (int iz = 0; iz < 2; iz++)
                #pragma unroll
                for (int iy = 0; iy < 2; iy++)
                #pragma unroll
                for (int ix = 0; ix < 2; ix++)
                    a[p8] += xin[iz * 4 + iy * 2 + ix] *
                             wr[((iz - oz + 1) * 3 + (iy - oy + 1)) * 3 + (ix - ox + 1)];
            }
        }
        float m = -1e30f;
        #pragma unroll
        for (int j = 0; j < 8; j++) {
            a[j] += __shfl_xor_sync(0xffffffffu, a[j], 1);
            a[j] += __shfl_xor_sync(0xffffffffu, a[j], 2);
            m = fmaxf(m, a[j]);
        }
        if (icg == 0) sm[FEATq + ocl] = lrelu(m + __ldg(&b5[ocl]));
    }
    __syncthreads();

    // heads: [64]->[6,32]->[6,16]->[6,4] -> normalize
    if (tid < 192) {
        const int h = tid >> 5, o = tid & 31;
        float acc = __ldg(&hb1[h * 32 + o]);
        const float* Wp = hW1 + (h * 64) * 32 + o;
        #pragma unroll
        for (int f = 0; f < 64; f++) acc += sm[FEATq + f] * __ldg(&Wp[f * 32]);
        sm[HSq + tid] = lrelu(acc);
    }
    __syncthreads();
    if (tid < 96) {
        const int h = tid >> 4, o = tid & 15;
        float acc = __ldg(&hb2[h * 16 + o]);
        const float* Wp  = hW2 + (h * 32) * 16 + o;
        const float* hin = sm + HSq + h * 32;
        #pragma unroll
        for (int f = 0; f < 32; f++) acc += hin[f] * __ldg(&Wp[f * 16]);
        sm[HSq + 192 + tid] = lrelu(acc);
    }
    __syncthreads();
    if (tid < 24) {
        const int h = tid >> 2, o = tid & 3;
        float acc = __ldg(&hb3[h * 4 + o]);
        const float* Wp  = hW3 + (h * 16) * 4 + o;
        const float* hin = sm + HSq + 192 + h * 16;
        #pragma unroll
        for (int f = 0; f < 16; f++) acc += hin[f] * __ldg(&Wp[f * 4]);
        sm[HSq + 288 + tid] = lrelu(acc);
    }
    __syncthreads();
    if (tid < 24) {
        const int h = tid >> 2;
        const float* hv = sm + HSq + 288 + h * 4;
        const float n = rsqrtf(hv[0] * hv[0] + hv[1] * hv[1] +
                               hv[2] * hv[2] + hv[3] * hv[3]);
        out[(size_t)b * 24 + tid] = sm[HSq + 288 + tid] * n;
    }
}

extern "C" void kernel_launch(void* const* d_in, const int* in_sizes, int n_in,
                              void* d_out, int out_size)
{
    const int B = in_sizes[0] / 32768;                  // 1024
    cudaFuncSetAttribute(k1_conv1, cudaFuncAttributeMaxDynamicSharedMemorySize,
                         10348 * 4);
    cudaFuncSetAttribute(k2_conv2, cudaFuncAttributeMaxDynamicSharedMemorySize,
                         11104 * 4);
    cudaFuncSetAttribute(k3_tail, cudaFuncAttributeMaxDynamicSharedMemorySize,
                         K3TOT * 4);
    k1_conv1<<<4 * B, 256, 10348 * 4>>>(
        (const float*)d_in[0], (const float*)d_in[1], (const float*)d_in[2]);
    k2_conv2<<<2 * B, 256, 11104 * 4>>>(
        (const float*)d_in[3], (const float*)d_in[4]);
    k3_tail<<<B, 256, K3TOT * 4>>>(
        (const float*)d_in[5],  (const float*)d_in[6],
        (const float*)d_in[7],  (const float*)d_in[8],
        (const float*)d_in[9],  (const float*)d_in[10],
        (const float*)d_in[11], (const float*)d_in[12],
        (const float*)d_in[13], (const float*)d_in[14],
        (const float*)d_in[15], (const float*)d_in[16],
        (float*)d_out);
}

// round 15
// speedup vs baseline: 2.5628x; 2.5628x over previous
#include <cuda_runtime.h>

#define NEG 0.2f
typedef unsigned long long ull;

// Inter-stage scratch (allocation-free rule: __device__ globals)
__device__ float g_buf1[1024 * 4 * 4096];   // [B][4][16^3]
__device__ float g_buf2[1024 * 8 * 512];    // [B][8][8^3]

__device__ __forceinline__ float lrelu(float x) { return x >= 0.0f ? x : NEG * x; }

__device__ __forceinline__ ull dup2(float v) {
    ull d; asm("mov.b64 %0, {%1, %1};" : "=l"(d) : "f"(v)); return d;
}
__device__ __forceinline__ void ffma2(ull& a, ull x, ull y) {
    asm("fma.rn.f32x2 %0, %1, %2, %0;" : "+l"(a) : "l"(x), "l"(y));
}
__device__ __forceinline__ void unpk(ull d, float& lo, float& hi) {
    asm("mov.b64 {%0, %1}, %2;" : "=f"(lo), "=f"(hi) : "l"(d));
}

// Load one 4-wide halo row from an NxN plane and dup each value into f32x2.
template <int N>
__device__ __forceinline__ void row_dup(const float* __restrict__ plane,
                                        int y, int e, bool mok, bool rok, ull* rd)
{
    const bool ok = (unsigned)y < (unsigned)N;
    const float2 zz = make_float2(0.0f, 0.0f);
    const float* row = plane + y * N;
    const float2 m = (ok && mok) ? *(const float2*)(row + e - 2) : zz;
    const float2 c = ok           ? *(const float2*)(row + e)     : zz;
    const float2 r = (ok && rok) ? *(const float2*)(row + e + 2) : zz;
    rd[0] = dup2(m.y); rd[1] = dup2(c.x); rd[2] = dup2(c.y); rd[3] = dup2(r.x);
}

// ---- jz-half conv: one pool-z half of a pooled cell (out z = base plane). ----
// Input slices s=0..2 relative to p0 (= out z - 1), each contributing kd = s.
// acc[g][jy*2 + jx] only (4 pool positions) -> 16 regs at NP=2.
template <int N, int NP>
__device__ __forceinline__ void conv_half(const float* __restrict__ p0, int PS,
                                          int px, int py,
                                          const ull* __restrict__ wb, int wstride,
                                          ull (&acc)[NP][4])
{
    const int by = 2 * py - 1, e = 2 * px;
    const bool mok = px >= 1, rok = (2 * px + 2) < N;
    #pragma unroll
    for (int s = 0; s < 3; s++) {
        const float* plane = p0 + s * PS;
        ull r0[4], r1[4];
        row_dup<N>(plane, by, e, mok, rok, r0);
        #pragma unroll
        for (int kh = 0; kh < 3; kh++) {
            ull* rlo = (kh & 1) ? r1 : r0;       // row kh
            ull* rhi = (kh & 1) ? r0 : r1;       // row kh+1
            row_dup<N>(plane, by + kh + 1, e, mok, rok, rhi);
            #pragma unroll
            for (int kw = 0; kw < 3; kw++) {
                const int t = (s * 3 + kh) * 3 + kw;
                ull wv[NP];
                #pragma unroll
                for (int g = 0; g < NP; g++) wv[g] = wb[g * wstride + t];
                #pragma unroll
                for (int jy = 0; jy < 2; jy++) {
                    const ull* rd = jy ? rhi : rlo;
                    #pragma unroll
                    for (int jx = 0; jx < 2; jx++)
                        #pragma unroll
                        for (int g = 0; g < NP; g++)
                            ffma2(acc[g][jy * 2 + jx], wv[g], rd[kw + jx]);
                }
            }
        }
    }
}

// ---- R8 helpers for k3 (full 4-slice patch, acc[NP][8]) ----
template <int N, int NP, int DZ>
__device__ __forceinline__ void conv_slice_dup(const float* __restrict__ plane,
                                               int px, int py,
                                               const ull* __restrict__ wb, int wstride,
                                               ull (&acc)[NP][8])
{
    const int by = 2 * py - 1, e = 2 * px;
    const bool mok = px >= 1, rok = (2 * px + 2) < N;
    ull r0[4], r1[4];
    row_dup<N>(plane, by, e, mok, rok, r0);
    #pragma unroll
    for (int kh = 0; kh < 3; kh++) {
        ull* rlo = (kh & 1) ? r1 : r0;
        ull* rhi = (kh & 1) ? r0 : r1;
        row_dup<N>(plane, by + kh + 1, e, mok, rok, rhi);
        #pragma unroll
        for (int kd = 0; kd < 3; kd++) {
            const int jz = DZ - kd;          // compile-time pruned
            if (jz < 0 || jz > 1) continue;
            #pragma unroll
            for (int kw = 0; kw < 3; kw++) {
                const int t = (kd * 3 + kh) * 3 + kw;
                ull wv[NP];
                #pragma unroll
                for (int g = 0; g < NP; g++) wv[g] = wb[g * wstride + t];
                #pragma unroll
                for (int jy = 0; jy < 2; jy++) {
                    const ull* rd = jy ? rhi : rlo;
                    #pragma unroll
                    for (int jx = 0; jx < 2; jx++)
                        #pragma unroll
                        for (int g = 0; g < NP; g++)
                            ffma2(acc[g][jz * 4 + jy * 2 + jx], wv[g], rd[kw + jx]);
                }
            }
        }
    }
}

__device__ __forceinline__ void finish_pair(const ull a[8], float blo, float bhi,
                                            float& olo, float& ohi) {
    float l, h, ml, mh;
    unpk(a[0], ml, mh);
    #pragma unroll
    for (int j = 1; j < 8; j++) {
        unpk(a[j], l, h);
        ml = fmaxf(ml, l); mh = fmaxf(mh, h);
    }
    olo = lrelu(ml + blo); ohi = lrelu(mh + bhi);
}

// ========= K1: conv1 (1->4) @32^3, 4-way z-split, jz-halved, 4 CTAs/SM =========
__global__ __launch_bounds__(256, 4)
void k1_conv1(const float* __restrict__ vox, const float* __restrict__ w1,
              const float* __restrict__ b1)
{
    extern __shared__ float sm[];
    float* slab = sm;                           // 10 planes * 1024
    ull*   w1u  = (ull*)(sm + 10240);           // 54 pairs {w_2g, w_2g+1}[27]
    const int tid = threadIdx.x;
    const int b = blockIdx.x >> 2, q = blockIdx.x & 3;
    {
        const float4* v4 = (const float4*)(vox + (size_t)b * 32768);
        float4* s4 = (float4*)slab;
        for (int i = tid; i < 2560; i += 256) {
            const int s = i >> 8, z = 8 * q - 1 + s;
            s4[i] = ((unsigned)z < 32u) ? v4[(z << 8) + (i & 255)]
                                        : make_float4(0, 0, 0, 0);
        }
        float2* wd = (float2*)w1u;
        for (int i = tid; i < 54; i += 256) {
            const int g = i / 27, t = i % 27;
            wd[i] = make_float2(w1[(2 * g) * 27 + t], w1[(2 * g + 1) * 27 + t]);
        }
    }
    __syncthreads();
    float bia[4];
    #pragma unroll
    for (int g = 0; g < 4; g++) bia[g] = __ldg(&b1[g]);

    #pragma unroll 1
    for (int it = 0; it < 4; it++) {
        const int c = tid + (it << 8);
        const int px = c & 15, py = (c >> 4) & 15, pzl = c >> 8;   // pzl 0..3
        float ml[2] = {-1e30f, -1e30f}, mh[2] = {-1e30f, -1e30f};
        #pragma unroll 1
        for (int H = 0; H < 2; H++) {
            ull acc[2][4];
            #pragma unroll
            for (int g = 0; g < 2; g++)
                #pragma unroll
                for (int j = 0; j < 4; j++) acc[g][j] = 0ull;
            // out z plane (local) = 2*pzl + H; input base plane = same (slab
            // plane p holds global z = 8q-1+p, so out-1+kd -> plane 2pzl+H+kd)
            conv_half<32, 2>(slab + ((2 * pzl + H) << 10), 1024, px, py,
                             w1u, 27, acc);
            #pragma unroll
            for (int g = 0; g < 2; g++)
                #pragma unroll
                for (int j = 0; j < 4; j++) {
                    float lo, hi; unpk(acc[g][j], lo, hi);
                    ml[g] = fmaxf(ml[g], lo); mh[g] = fmaxf(mh[g], hi);
                }
        }
        #pragma unroll
        for (int g = 0; g < 2; g++) {
            const int cell = ((q * 4 + pzl) << 8) + (py << 4) + px;
            g_buf1[(((size_t)b * 4 + 2 * g) << 12) + cell]     = lrelu(ml[g] + bia[2 * g]);
            g_buf1[(((size_t)b * 4 + 2 * g + 1) << 12) + cell] = lrelu(mh[g] + bia[2 * g + 1]);
        }
    }
}

// ========= K2: conv2 (4->8) @16^3, z-split, jz-halved, 4 CTAs/SM =========
__global__ __launch_bounds__(256, 4)
void k2_conv2(const float* __restrict__ w2, const float* __restrict__ b2)
{
    extern __shared__ float sm[];
    float* slab = sm;                           // 4 ic * 10 planes * 256
    ull*   w2u  = (ull*)(sm + 10240);           // 432 pairs [g(4)][ic(4)][27]
    const int tid = threadIdx.x;
    const int b = blockIdx.x >> 1, h = blockIdx.x & 1;
    {
        const float4* g4 = (const float4*)g_buf1;
        float4* s4 = (float4*)slab;
        for (int i = tid; i < 2560; i += 256) {
            const int ic = i / 640, rem = i - ic * 640;
            const int s = rem >> 6, z = 8 * h - 1 + s;
            s4[i] = ((unsigned)z < 16u)
                ? g4[(((size_t)b * 4 + ic) << 10) + (z << 6) + (rem & 63)]
                : make_float4(0, 0, 0, 0);
        }
        float2* wd = (float2*)w2u;
        for (int i = tid; i < 432; i += 256) {
            const int g = i / 108, rem = i % 108, ic = rem / 27, t = rem % 27;
            wd[i] = make_float2(w2[((2 * g) * 4 + ic) * 27 + t],
                                w2[((2 * g + 1) * 4 + ic) * 27 + t]);
        }
    }
    __syncthreads();
    const int px = tid & 7, py = (tid >> 3) & 7, pzl = tid >> 6;

    #pragma unroll 1
    for (int opass = 0; opass < 2; opass++) {
        float ml[2] = {-1e30f, -1e30f}, mh[2] = {-1e30f, -1e30f};
        #pragma unroll 1
        for (int H = 0; H < 2; H++) {
            ull acc[2][4];
            #pragma unroll
            for (int g = 0; g < 2; g++)
                #pragma unroll
                for (int j = 0; j < 4; j++) acc[g][j] = 0ull;
            #pragma unroll 1
            for (int ic = 0; ic < 4; ic++)
                conv_half<16, 2>(slab + ic * 2560 + ((2 * pzl + H) << 8), 256,
                                 px, py, w2u + ((opass * 2) * 4 + ic) * 27, 108, acc);
            #pragma unroll
            for (int g = 0; g < 2; g++)
                #pragma unroll
                for (int j = 0; j < 4; j++) {
                    float lo, hi; unpk(acc[g][j], lo, hi);
                    ml[g] = fmaxf(ml[g], lo); mh[g] = fmaxf(mh[g], hi);
                }
        }
        #pragma unroll
        for (int g = 0; g < 2; g++) {
            const int oc0 = 2 * (opass * 2 + g);
            const int cell = ((4 * h + pzl) << 6) + (py << 3) + px;
            g_buf2[(((size_t)b * 8 + oc0) << 9) + cell]     = lrelu(ml[g] + __ldg(&b2[oc0]));
            g_buf2[(((size_t)b * 8 + oc0 + 1) << 9) + cell] = lrelu(mh[g] + __ldg(&b2[oc0 + 1]));
        }
    }
}

// ======================= K3: conv3..conv5 + heads (R8, proven) ==============
#define ZPAD  0            // 64 zeros (OOB z-plane source)
#define R0    64           // phase A: {w3 pairs 6912 | buf2 4096}; phase B: w4
#define BUF3q (64 + 13824)
#define BUF4q 14912
#define FEATq 15168
#define HSq   15232
#define K3TOT 15552        // floats -> 62208 B

__global__ __launch_bounds__(256, 3)
void k3_tail(const float* __restrict__ w3, const float* __restrict__ b3,
             const float* __restrict__ w4, const float* __restrict__ b4,
             const float* __restrict__ w5, const float* __restrict__ b5,
             const float* __restrict__ hW1, const float* __restrict__ hb1,
             const float* __restrict__ hW2, const float* __restrict__ hb2,
             const float* __restrict__ hW3, const float* __restrict__ hb3,
             float* __restrict__ out)
{
    extern __shared__ float sm[];
    const int tid = threadIdx.x, b = blockIdx.x;
    ull*   w3u  = (ull*)(sm + R0);
    float* buf2 = sm + R0 + 6912;
    {
        if (tid < 64) sm[ZPAD + tid] = 0.0f;
        const float4* g4 = (const float4*)(g_buf2 + (size_t)b * 4096);
        float4* s4 = (float4*)buf2;
        for (int i = tid; i < 1024; i += 256) s4[i] = g4[i];
        float2* wd = (float2*)w3u;
        for (int i = tid; i < 1728; i += 256) {
            const int g = i / 216, rem = i % 216, ic = rem / 27, t = rem % 27;
            wd[i] = make_float2(w3[((2 * g) * 8 + ic) * 27 + t],
                                w3[((2 * g + 1) * 8 + ic) * 27 + t]);
        }
    }
    __syncthreads();

    // conv3 (8->16) @8^3 -> buf3 [16][4^3]
    {
        const int grp = tid >> 6, cell = tid & 63;
        const int px = cell & 3, py = (cell >> 2) & 3, pz = cell >> 4;
        ull acc[2][8];
        #pragma unroll
        for (int g = 0; g < 2; g++)
            #pragma unroll
            for (int j = 0; j < 8; j++) acc[g][j] = 0ull;
        const int z0 = 2 * pz - 1;
        #pragma unroll 1
        for (int ic = 0; ic < 8; ic++) {
            const float* chan = buf2 + ic * 512;
            const ull*   wp   = w3u + ((2 * grp) * 8 + ic) * 27;
            conv_slice_dup<8, 2, 0>(((unsigned)z0       < 8u) ? chan + (z0 << 6)       : sm + ZPAD, px, py, wp, 216, acc);
            conv_slice_dup<8, 2, 1>(chan + ((z0 + 1) << 6), px, py, wp, 216, acc);
            conv_slice_dup<8, 2, 2>(chan + ((z0 + 2) << 6), px, py, wp, 216, acc);
            conv_slice_dup<8, 2, 3>(((unsigned)(z0 + 3) < 8u) ? chan + ((z0 + 3) << 6) : sm + ZPAD, px, py, wp, 216, acc);
        }
        #pragma unroll
        for (int g = 0; g < 2; g++) {
            const int oc0 = 4 * grp + 2 * g;
            float olo, ohi;
            finish_pair(acc[g], __ldg(&b3[oc0]), __ldg(&b3[oc0 + 1]), olo, ohi);
            sm[BUF3q + oc0 * 64 + cell]       = olo;
            sm[BUF3q + (oc0 + 1) * 64 + cell] = ohi;
        }
    }
    __syncthreads();

    // stage w4 pairs into R0 (w3/buf2 dead)
    {
        float2* wd = (float2*)(sm + R0);
        for (int i = tid; i < 6912; i += 256) {
            const int p = i / 432, rem = i % 432, ic = rem / 27, t = rem % 27;
            wd[i] = make_float2(w4[((2 * p) * 16 + ic) * 27 + t],
                                w4[((2 * p + 1) * 16 + ic) * 27 + t]);
        }
    }
    __syncthreads();

    // conv4 (16->32) @4^3 -> buf4 [32][2^3]
    {
        const ull* w4u = (const ull*)(sm + R0);
        const int p = tid >> 4, cell = (tid >> 1) & 7, icg = tid & 1;
        const int px = cell & 1, py = (cell >> 1) & 1, pz = cell >> 2;
        ull acc[1][8];
        #pragma unroll
        for (int j = 0; j < 8; j++) acc[0][j] = 0ull;
        const int z0 = 2 * pz - 1;
        #pragma unroll 1
        for (int k = 0; k < 8; k++) {
            const int ic = icg * 8 + k;
            const float* chan = sm + BUF3q + ic * 64;
            const ull*   wp   = w4u + (p * 16 + ic) * 27;
            conv_slice_dup<4, 1, 0>(((unsigned)z0       < 4u) ? chan + (z0 << 4)       : sm + ZPAD, px, py, wp, 0, acc);
            conv_slice_dup<4, 1, 1>(chan + ((z0 + 1) << 4), px, py, wp, 0, acc);
            conv_slice_dup<4, 1, 2>(chan + ((z0 + 2) << 4), px, py, wp, 0, acc);
            conv_slice_dup<4, 1, 3>(((unsigned)(z0 + 3) < 4u) ? chan + ((z0 + 3) << 4) : sm + ZPAD, px, py, wp, 0, acc);
        }
        float mlo = -1e30f, mhi = -1e30f;
        #pragma unroll
        for (int j = 0; j < 8; j++) {
            float lo, hi; unpk(acc[0][j], lo, hi);
            lo += __shfl_xor_sync(0xffffffffu, lo, 1);
            hi += __shfl_xor_sync(0xffffffffu, hi, 1);
            mlo = fmaxf(mlo, lo); mhi = fmaxf(mhi, hi);
        }
        if (icg == 0) {
            sm[BUF4q + (2 * p) * 8 + cell]     = lrelu(mlo + __ldg(&b4[2 * p]));
            sm[BUF4q + (2 * p + 1) * 8 + cell] = lrelu(mhi + __ldg(&b4[2 * p + 1]));
        }
    }
    __syncthreads();

    // conv5 (32->64) @2^3 -> feat[64]
    {
        const int ocl = tid >> 2, icg = tid & 3;
        float a[8];
        #pragma unroll
        for (int j = 0; j < 8; j++) a[j] = 0.0f;
        #pragma unroll 1
        for (int k = 0; k < 8; k++) {
            const int ic = icg * 8 + k;
            float xin[8];
            #pragma unroll
            for (int j = 0; j < 8; j++) xin[j] = sm[BUF4q + ic * 8 + j];
            float wr[27];
            const float* wp = w5 + (ocl * 32 + ic) * 27;
            #pragma unroll
            for (int t = 0; t < 27; t++) wr[t] = __ldg(&wp[t]);
            #pragma unroll
            for (int p8 = 0; p8 < 8; p8++) {
                const int oz = p8 >> 2, oy = (p8 >> 1) & 1, ox = p8 & 1;
                #pragma unroll
                for (int iz = 0; iz < 2; iz++)
                #pragma unroll
                for (int iy = 0; iy < 2; iy++)
                #pragma unroll
                for (int ix = 0; ix < 2; ix++)
                    a[p8] += xin[iz * 4 + iy * 2 + ix] *
                             wr[((iz - oz + 1) * 3 + (iy - oy + 1)) * 3 + (ix - ox + 1)];
            }
        }
        float m = -1e30f;
        #pragma unroll
        for (int j = 0; j < 8; j++) {
            a[j] += __shfl_xor_sync(0xffffffffu, a[j], 1);
            a[j] += __shfl_xor_sync(0xffffffffu, a[j], 2);
            m = fmaxf(m, a[j]);
        }
        if (icg == 0) sm[FEATq + ocl] = lrelu(m + __ldg(&b5[ocl]));
    }
    __syncthreads();

    // heads: [64]->[6,32]->[6,16]->[6,4] -> normalize
    if (tid < 192) {
        const int h = tid >> 5, o = tid & 31;
        float acc = __ldg(&hb1[h * 32 + o]);
        const float* Wp = hW1 + (h * 64) * 32 + o;
        #pragma unroll
        for (int f = 0; f < 64; f++) acc += sm[FEATq + f] * __ldg(&Wp[f * 32]);
        sm[HSq + tid] = lrelu(acc);
    }
    __syncthreads();
    if (tid < 96) {
        const int h = tid >> 4, o = tid & 15;
        float acc = __ldg(&hb2[h * 16 + o]);
        const float* Wp  = hW2 + (h * 32) * 16 + o;
        const float* hin = sm + HSq + h * 32;
        #pragma unroll
        for (int f = 0; f < 32; f++) acc += hin[f] * __ldg(&Wp[f * 16]);
        sm[HSq + 192 + tid] = lrelu(acc);
    }
    __syncthreads();
    if (tid < 24) {
        const int h = tid >> 2, o = tid & 3;
        float acc = __ldg(&hb3[h * 4 + o]);
        const float* Wp  = hW3 + (h * 16) * 4 + o;
        const float* hin = sm + HSq + 192 + h * 16;
        #pragma unroll
        for (int f = 0; f < 16; f++) acc += hin[f] * __ldg(&Wp[f * 4]);
        sm[HSq + 288 + tid] = lrelu(acc);
    }
    __syncthreads();
    if (tid < 24) {
        const int h = tid >> 2;
        const float* hv = sm + HSq + 288 + h * 4;
        const float n = rsqrtf(hv[0] * hv[0] + hv[1] * hv[1] +
                               hv[2] * hv[2] + hv[3] * hv[3]);
        out[(size_t)b * 24 + tid] = sm[HSq + 288 + tid] * n;
    }
}

extern "C" void kernel_launch(void* const* d_in, const int* in_sizes, int n_in,
                              void* d_out, int out_size)
{
    const int B = in_sizes[0] / 32768;                  // 1024
    cudaFuncSetAttribute(k1_conv1, cudaFuncAttributeMaxDynamicSharedMemorySize,
                         10348 * 4);
    cudaFuncSetAttribute(k2_conv2, cudaFuncAttributeMaxDynamicSharedMemorySize,
                         11104 * 4);
    cudaFuncSetAttribute(k3_tail, cudaFuncAttributeMaxDynamicSharedMemorySize,
                         K3TOT * 4);
    k1_conv1<<<4 * B, 256, 10348 * 4>>>(
        (const float*)d_in[0], (const float*)d_in[1], (const float*)d_in[2]);
    k2_conv2<<<2 * B, 256, 11104 * 4>>>(
        (const float*)d_in[3], (const float*)d_in[4]);
    k3_tail<<<B, 256, K3TOT * 4>>>(
        (const float*)d_in[5],  (const float*)d_in[6],
        (const float*)d_in[7],  (const float*)d_in[8],
        (const float*)d_in[9],  (const float*)d_in[10],
        (const float*)d_in[11], (const float*)d_in[12],
        (const float*)d_in[13], (const float*)d_in[14],
        (const float*)d_in[15], (const float*)d_in[16],
        (float*)d_out);
}